// round 9
// baseline (speedup 1.0000x reference)
#include <cuda_runtime.h>

// CapsuleConvTranspose2d (2,64,32,32) -> (2,64,64,64): stride-2 3x3 transposed
// conv into 8 out-capsules x 8 dims, 3-iter k-means routing, squash, bias.
//
// patch[n,c,kh,kw,p,q] = x[n,c,(p+kh-1)/2,(q+kw-1)/2] iff (p+kh-1) even & in
// range, else 0. Valid kh depends only on parity of p (even->{1}, odd->{0,2});
// same for q/kw. Border taps (p or q = 63, tap 2) zero-filled: a zero prior
// routes identically (exp(0)=1 in Z), counted in NZEROS.
//
// Softmax without max subtraction (logits O(1) here, fp32-safe); zero priors
// add exactly NZEROS to Z.
//
// All 8-dim vector math stays in packed f32x2 registers (SASS FFMA2 via PTX
// fma.rn.f32x2), INCLUDING the cross-lane reductions: the width-8 all-reduce
// is a butterfly on the 4 packed regs using 64-bit shuffles (24 SHFL + 12
// add2, no selects, no pack/unpack).
//
// Kernel 1 (prep): transpose x -> xt[n][i][j][c]; pack weights per parity
// class wpk[cls][(l*8+g)*ntap+tp][m] (flipped taps baked in).
// Kernel 2: 64 threads/pixel, g=tid>>3, r=tid&7; lane r owns the ntap priors
// of tap tp at fields f0 + k*(8/ntap), in registers. EE/EO/OE read x directly
// from xt (no smem/sync); OO stages x in smem (pitch-34 layout -> LDS.64,
// conflict-free).

typedef unsigned long long ull;

__device__ __forceinline__ ull pack2(float lo, float hi) {
    ull r; asm("mov.b64 %0,{%1,%2};" : "=l"(r) : "f"(lo), "f"(hi)); return r;
}
__device__ __forceinline__ void unpack2(ull v, float& lo, float& hi) {
    asm("mov.b64 {%0,%1},%2;" : "=f"(lo), "=f"(hi) : "l"(v));
}
__device__ __forceinline__ ull fma2(ull a, ull b, ull c) {
    ull d; asm("fma.rn.f32x2 %0,%1,%2,%3;" : "=l"(d) : "l"(a), "l"(b), "l"(c)); return d;
}
__device__ __forceinline__ ull mul2(ull a, ull b) {
    ull d; asm("mul.rn.f32x2 %0,%1,%2;" : "=l"(d) : "l"(a), "l"(b)); return d;
}
__device__ __forceinline__ ull add2(ull a, ull b) {
    ull d; asm("add.rn.f32x2 %0,%1,%2;" : "=l"(d) : "l"(a), "l"(b)); return d;
}

__device__ float g_xt[2 * 32 * 32 * 64];
__device__ __align__(16) float g_wpk[4608];   // cls bases: 0,512,1536,2560

__global__ __launch_bounds__(256)
void prep_kernel(const float* __restrict__ x, const float* __restrict__ wt)
{
    const int b = blockIdx.x;
    const int t = threadIdx.x;
    if (b < 128) {
        // transpose half the channels of one (n,i) row: x[n][c][i][j] -> xt[n][i][j][c]
        __shared__ float s[32][33];
        const int n  = b >> 6;
        const int i  = (b >> 1) & 31;
        const int ch = (b & 1) << 5;
        {
            int c = t >> 3, j4 = (t & 7) << 2;
            float4 v = *(const float4*)&x[((n * 64 + ch + c) * 32 + i) * 32 + j4];
            s[c][j4] = v.x; s[c][j4 + 1] = v.y; s[c][j4 + 2] = v.z; s[c][j4 + 3] = v.w;
        }
        __syncthreads();
        #pragma unroll
        for (int k = 0; k < 4; k++) {
            int idx = t + k * 256;
            int j = idx >> 5, c = idx & 31;
            g_xt[((n * 32 + i) * 32 + j) * 64 + ch + c] = s[c][j];
        }
    } else {
        // pack weights: wpk[base + ((l*8+g)*ntap + tp)*8 + m]
        for (int w = t; w < 4608; w += 256) {
            int cls, rem, ntap;
            if (w < 512)       { cls = 0; rem = w;        ntap = 1; }
            else if (w < 1536) { cls = 1; rem = w - 512;  ntap = 2; }
            else if (w < 2560) { cls = 2; rem = w - 1536; ntap = 2; }
            else               { cls = 3; rem = w - 2560; ntap = 4; }
            int m  = rem & 7;
            int e  = rem >> 3;          // (l*8+g)*ntap + tp
            int tp = e % ntap;
            int lg = e / ntap;          // l*8 + g
            int kh, kw;
            if (cls == 0)      { kh = 1;              kw = 1; }
            else if (cls == 1) { kh = 1;              kw = tp << 1; }
            else if (cls == 2) { kh = tp << 1;        kw = 1; }
            else               { kh = (tp >> 1) << 1; kw = (tp & 1) << 1; }
            int woff = (2 - kh) * 3 + (2 - kw);       // flipped kernel tap
            g_wpk[w] = wt[(lg * 8 + m) * 9 + woff];
        }
    }
}

// packed width-8 all-reduce of 4 f32x2 regs: 24 shfl + 12 add2, no selects
__device__ __forceinline__ void allreduce8p(ull v[4])
{
    const unsigned FULL = 0xffffffffu;
    #pragma unroll
    for (int d = 1; d < 8; d <<= 1)
        #pragma unroll
        for (int j = 0; j < 4; j++)
            v[j] = add2(v[j], __shfl_xor_sync(FULL, v[j], d, 8));
}

// reduce-scatter over width 8: returns fully-summed component r (7 shfl)
__device__ __forceinline__ float reduce_scatter8(const float v[8], int r)
{
    const unsigned FULL = 0xffffffffu;
    const bool b4 = (r & 4) != 0, b2 = (r & 2) != 0, b1 = (r & 1) != 0;
    float w[4], u[2];
    #pragma unroll
    for (int i = 0; i < 4; i++) {
        float send = b4 ? v[i] : v[4 + i];
        float keep = b4 ? v[4 + i] : v[i];
        w[i] = keep + __shfl_xor_sync(FULL, send, 4, 8);
    }
    #pragma unroll
    for (int i = 0; i < 2; i++) {
        float send = b2 ? w[i] : w[2 + i];
        float keep = b2 ? w[2 + i] : w[i];
        u[i] = keep + __shfl_xor_sync(FULL, send, 2, 8);
    }
    float send = b1 ? u[0] : u[1];
    float keep = b1 ? u[1] : u[0];
    return keep + __shfl_xor_sync(FULL, send, 1, 8);
}

// routing + squash + store; priors packed: pri2[k][j] = (m=2j, m=2j+1)
template<int CNT>
__device__ __forceinline__ void route_and_store(
    ull pri2[CNT][4], int n, int p, int q,
    const float* __restrict__ bs, float* __restrict__ y)
{
    constexpr float NZEROS = (float)(72 - 8 * CNT);
    const unsigned FULL = 0xffffffffu;
    const int tid = threadIdx.x;
    const int r = tid & 7;

    // init: mean over all 72 (zeros included in divisor); stays packed
    ull o2[4];
    #pragma unroll
    for (int j = 0; j < 4; j++) o2[j] = pri2[0][j];
    #pragma unroll
    for (int k = 1; k < CNT; k++)
        #pragma unroll
        for (int j = 0; j < 4; j++) o2[j] = add2(o2[j], pri2[k][j]);
    allreduce8p(o2);
    {
        const ull c72 = pack2(1.0f / 72.0f, 1.0f / 72.0f);
        #pragma unroll
        for (int j = 0; j < 4; j++) o2[j] = mul2(o2[j], c72);
    }

    #pragma unroll
    for (int it = 0; it < 2; it++) {
        // ||o||^2 (packed dot)
        ull t = mul2(o2[0], o2[0]);
        t = fma2(o2[1], o2[1], t);
        t = fma2(o2[2], o2[2], t);
        t = fma2(o2[3], o2[3], t);
        float ta, tb; unpack2(t, ta, tb);
        float inv = rsqrtf(fmaxf(ta + tb, 1e-24f));

        float e[CNT];
        float z = 0.f;
        #pragma unroll
        for (int k = 0; k < CNT; k++) {
            ull s = mul2(pri2[k][0], o2[0]);
            s = fma2(pri2[k][1], o2[1], s);
            s = fma2(pri2[k][2], o2[2], s);
            s = fma2(pri2[k][3], o2[3], s);
            float sa, sb; unpack2(s, sa, sb);
            e[k] = __expf((sa + sb) * inv);
            z += e[k];
        }
        z += __shfl_xor_sync(FULL, z, 1, 8);
        z += __shfl_xor_sync(FULL, z, 2, 8);
        z += __shfl_xor_sync(FULL, z, 4, 8);
        z += NZEROS;

        ull acc2[4];
        {
            ull e2 = pack2(e[0], e[0]);
            #pragma unroll
            for (int j = 0; j < 4; j++) acc2[j] = mul2(e2, pri2[0][j]);
        }
        #pragma unroll
        for (int k = 1; k < CNT; k++) {
            ull e2 = pack2(e[k], e[k]);
            #pragma unroll
            for (int j = 0; j < 4; j++) acc2[j] = fma2(e2, pri2[k][j], acc2[j]);
        }
        allreduce8p(acc2);

        float rz = __fdividef(1.0f, z);
        ull rz2 = pack2(rz, rz);
        #pragma unroll
        for (int j = 0; j < 4; j++) o2[j] = mul2(acc2[j], rz2);
    }

    // final iteration: reduce-scatter only (lane r keeps component r)
    {
        ull t = mul2(o2[0], o2[0]);
        t = fma2(o2[1], o2[1], t);
        t = fma2(o2[2], o2[2], t);
        t = fma2(o2[3], o2[3], t);
        float ta, tb; unpack2(t, ta, tb);
        float inv = rsqrtf(fmaxf(ta + tb, 1e-24f));

        float e[CNT];
        float z = 0.f;
        #pragma unroll
        for (int k = 0; k < CNT; k++) {
            ull s = mul2(pri2[k][0], o2[0]);
            s = fma2(pri2[k][1], o2[1], s);
            s = fma2(pri2[k][2], o2[2], s);
            s = fma2(pri2[k][3], o2[3], s);
            float sa, sb; unpack2(s, sa, sb);
            e[k] = __expf((sa + sb) * inv);
            z += e[k];
        }
        z += __shfl_xor_sync(FULL, z, 1, 8);
        z += __shfl_xor_sync(FULL, z, 2, 8);
        z += __shfl_xor_sync(FULL, z, 4, 8);
        z += NZEROS;

        ull acc2[4];
        {
            ull e2 = pack2(e[0], e[0]);
            #pragma unroll
            for (int j = 0; j < 4; j++) acc2[j] = mul2(e2, pri2[0][j]);
        }
        #pragma unroll
        for (int k = 1; k < CNT; k++) {
            ull e2 = pack2(e[k], e[k]);
            #pragma unroll
            for (int j = 0; j < 4; j++) acc2[j] = fma2(e2, pri2[k][j], acc2[j]);
        }
        float acc[8];
        #pragma unroll
        for (int j = 0; j < 4; j++) unpack2(acc2[j], acc[2 * j], acc[2 * j + 1]);

        float s   = reduce_scatter8(acc, r);
        float orr = s * __fdividef(1.0f, z);

        float sq = orr * orr;
        sq += __shfl_xor_sync(FULL, sq, 1, 8);
        sq += __shfl_xor_sync(FULL, sq, 2, 8);
        sq += __shfl_xor_sync(FULL, sq, 4, 8);

        float scale = sq / ((1.0f + sq) * sqrtf(sq + 1e-12f));
        y[((n * 64 + tid) * 64 + p) * 64 + q] = orr * scale + bs[tid];
    }
}

__device__ __forceinline__ void load8(float dst[8], const float* src, bool valid)
{
    if (valid) {
        float4 u0 = *(const float4*)(src);
        float4 u1 = *(const float4*)(src + 4);
        dst[0] = u0.x; dst[1] = u0.y; dst[2] = u0.z; dst[3] = u0.w;
        dst[4] = u1.x; dst[5] = u1.y; dst[6] = u1.z; dst[7] = u1.w;
    } else {
        #pragma unroll
        for (int i = 0; i < 8; i++) dst[i] = 0.f;
    }
}

// NTAP<=2 classes: x direct from g_xt (registers), packed-FMA priors.
template<int NTAP, int BASE>
__device__ __forceinline__ void caps_direct(
    int n, int p, int q, int i0, int j0, bool ivar,   // ivar: tap varies i (OE)
    const float* __restrict__ bs, float* __restrict__ y)
{
    const int tid = threadIdx.x;
    const int g = tid >> 3;
    const int r = tid & 7;
    const int tp = r & (NTAP - 1);
    const int f0 = r / NTAP;

    float xr[NTAP][8];   // [k][l], fields f0 + k*(8/NTAP)
    if (NTAP == 1) {
        const float* xb = g_xt + ((n * 32 + i0) * 32 + j0) * 64 + f0 * 8;
        load8(xr[0], xb, true);
    } else {
        int i = ivar ? (i0 + tp) : i0;
        int j = ivar ? j0 : (j0 + tp);
        bool valid = (i < 32) && (j < 32);     // tap 2 at p/q == 63
        const float* xb = g_xt + ((n * 32 + i) * 32 + j) * 64;
        load8(xr[0], xb + f0 * 8, valid);
        load8(xr[1], xb + (f0 + 4) * 8, valid);
    }

    const float* wrow = g_wpk + BASE + (g * NTAP + tp) * 8;

    ull pri2[NTAP][4];
    #pragma unroll
    for (int k = 0; k < NTAP; k++)
        #pragma unroll
        for (int j = 0; j < 4; j++) pri2[k][j] = 0ull;

    #pragma unroll
    for (int l = 0; l < 8; l++) {
        const ulonglong2* wp = (const ulonglong2*)(wrow + l * (64 * NTAP));
        ulonglong2 wa = wp[0];            // (m0,m1),(m2,m3)
        ulonglong2 wb = wp[1];            // (m4,m5),(m6,m7)
        #pragma unroll
        for (int k = 0; k < NTAP; k++) {
            ull xx = pack2(xr[k][l], xr[k][l]);
            pri2[k][0] = fma2(xx, wa.x, pri2[k][0]);
            pri2[k][1] = fma2(xx, wa.y, pri2[k][1]);
            pri2[k][2] = fma2(xx, wb.x, pri2[k][2]);
            pri2[k][3] = fma2(xx, wb.y, pri2[k][3]);
        }
    }

    route_and_store<NTAP>(pri2, n, p, q, bs, y);
}

// OO class: x staged in smem, layout s_x[f*34 + pos*8 + l] -> LDS.64 reads,
// conflict-free (banks 2f + 8tp + l, distinct per instruction), 8B-aligned.
__device__ __forceinline__ void caps_oo(
    int n, int p, int q, float* __restrict__ s_x,
    const float* __restrict__ bs, float* __restrict__ y)
{
    const int tid = threadIdx.x;
    const int g = tid >> 3;
    const int r = tid & 7;

    const int i0 = p >> 1, j0 = q >> 1;   // p,q odd: (p-1)/2
    const int fw = tid >> 3, lw = tid & 7;
    #pragma unroll
    for (int pos = 0; pos < 4; pos++) {
        int i = i0 + (pos >> 1);
        int j = j0 + (pos & 1);
        bool valid = (i < 32) && (j < 32);
        float v = valid ? g_xt[((n * 32 + i) * 32 + j) * 64 + tid] : 0.f;
        s_x[fw * 34 + pos * 8 + lw] = v;
    }
    __syncthreads();

    const int tp = r & 3;
    const int f0 = r >> 2;
    const float* wrow = g_wpk + 2560 + (g * 4 + tp) * 8;
    const float* xrow = s_x + f0 * 34 + tp * 8;   // field f0+2k -> + k*68

    ull pri2[4][4];
    #pragma unroll
    for (int k = 0; k < 4; k++)
        #pragma unroll
        for (int j = 0; j < 4; j++) pri2[k][j] = 0ull;

    #pragma unroll
    for (int l2 = 0; l2 < 4; l2++) {
        const int l = l2 * 2;
        const ulonglong2* wpA = (const ulonglong2*)(wrow + l * 256);
        const ulonglong2* wpB = (const ulonglong2*)(wrow + (l + 1) * 256);
        ulonglong2 wa = wpA[0], wb = wpA[1];
        ulonglong2 wc = wpB[0], wd = wpB[1];
        #pragma unroll
        for (int k = 0; k < 4; k++) {
            float2 xv = *(const float2*)(xrow + k * 68 + l);   // LDS.64
            ull x0 = pack2(xv.x, xv.x);
            ull x1 = pack2(xv.y, xv.y);
            pri2[k][0] = fma2(x0, wa.x, pri2[k][0]);
            pri2[k][1] = fma2(x0, wa.y, pri2[k][1]);
            pri2[k][2] = fma2(x0, wb.x, pri2[k][2]);
            pri2[k][3] = fma2(x0, wb.y, pri2[k][3]);
            pri2[k][0] = fma2(x1, wc.x, pri2[k][0]);
            pri2[k][1] = fma2(x1, wc.y, pri2[k][1]);
            pri2[k][2] = fma2(x1, wd.x, pri2[k][2]);
            pri2[k][3] = fma2(x1, wd.y, pri2[k][3]);
        }
    }

    route_and_store<4>(pri2, n, p, q, bs, y);
}

__global__ __launch_bounds__(64, 16)
void caps_kernel(const float* __restrict__ bs, float* __restrict__ y)
{
    __shared__ float s_x[8 * 34];

    const int pix = blockIdx.x;
    const int q = pix & 63;
    const int p = (pix >> 6) & 63;
    const int n = pix >> 12;

    const bool po = (p & 1) != 0;
    const bool qo = (q & 1) != 0;

    if (!po && !qo)
        caps_direct<1, 0>(n, p, q, p >> 1, q >> 1, false, bs, y);
    else if (!po)
        caps_direct<2, 512>(n, p, q, p >> 1, q >> 1, false, bs, y);   // j = j0+tp
    else if (!qo)
        caps_direct<2, 1536>(n, p, q, p >> 1, q >> 1, true, bs, y);   // i = i0+tp
    else
        caps_oo(n, p, q, s_x, bs, y);
}

extern "C" void kernel_launch(void* const* d_in, const int* in_sizes, int n_in,
                              void* d_out, int out_size) {
    const float* x  = (const float*)d_in[0];
    const float* wt = (const float*)d_in[1];
    const float* bs = (const float*)d_in[2];
    float* y = (float*)d_out;
    prep_kernel<<<129, 256>>>(x, wt);
    caps_kernel<<<2 * 64 * 64, 64>>>(bs, y);
}

// round 10
// speedup vs baseline: 1.0083x; 1.0083x over previous
#include <cuda_runtime.h>

// CapsuleConvTranspose2d (2,64,32,32) -> (2,64,64,64): stride-2 3x3 transposed
// conv into 8 out-capsules x 8 dims, 3-iter k-means routing, squash, bias.
//
// patch[n,c,kh,kw,p,q] = x[n,c,(p+kh-1)/2,(q+kw-1)/2] iff (p+kh-1) even & in
// range, else 0. Valid kh depends only on parity of p (even->{1}, odd->{0,2});
// same for q/kw. Border taps (p or q = 63, tap 2) zero-filled: a zero prior
// routes identically (exp(0)=1 in Z), counted in NZEROS.
//
// Routing algebra: iterations only consume out/||out||, and out = acc/Z, so Z
// CANCELS in iterations 0..1 (and the init's 1/72 cancels too). Z is computed
// only in the final iteration, where the magnitude feeds squash. Softmax is
// computed without max subtraction (logits O(1), fp32-safe); zero priors add
// exactly NZEROS to Z.
//
// Vector math is packed f32x2 (SASS FFMA2 via PTX fma.rn.f32x2). Cross-lane
// width-8 reductions use packed reduce-scatter (7 wavefronts) + all-gather
// (7 wavefronts) instead of a full butterfly (48).
//
// Kernel 1 (prep): transpose x -> xt[n][i][j][c]; pack weights per parity
// class wpk[cls][(l*8+g)*ntap+tp][m] (flipped taps baked in).
// Kernel 2: 64 threads/pixel, g=tid>>3, r=tid&7; lane r owns the ntap priors
// of tap tp at fields f0 + k*(8/ntap), in registers. EE/EO/OE read x directly
// from xt (no smem/sync); OO stages x in smem (pitch-34, LDS.64, conflict-free).

typedef unsigned long long ull;

__device__ __forceinline__ ull pack2(float lo, float hi) {
    ull r; asm("mov.b64 %0,{%1,%2};" : "=l"(r) : "f"(lo), "f"(hi)); return r;
}
__device__ __forceinline__ void unpack2(ull v, float& lo, float& hi) {
    asm("mov.b64 {%0,%1},%2;" : "=f"(lo), "=f"(hi) : "l"(v));
}
__device__ __forceinline__ ull fma2(ull a, ull b, ull c) {
    ull d; asm("fma.rn.f32x2 %0,%1,%2,%3;" : "=l"(d) : "l"(a), "l"(b), "l"(c)); return d;
}
__device__ __forceinline__ ull mul2(ull a, ull b) {
    ull d; asm("mul.rn.f32x2 %0,%1,%2;" : "=l"(d) : "l"(a), "l"(b)); return d;
}
__device__ __forceinline__ ull add2(ull a, ull b) {
    ull d; asm("add.rn.f32x2 %0,%1,%2;" : "=l"(d) : "l"(a), "l"(b)); return d;
}

__device__ float g_xt[2 * 32 * 32 * 64];
__device__ __align__(16) float g_wpk[4608];   // cls bases: 0,512,1536,2560

__global__ __launch_bounds__(256)
void prep_kernel(const float* __restrict__ x, const float* __restrict__ wt)
{
    const int b = blockIdx.x;
    const int t = threadIdx.x;
    if (b < 128) {
        // transpose half the channels of one (n,i) row: x[n][c][i][j] -> xt[n][i][j][c]
        __shared__ float s[32][33];
        const int n  = b >> 6;
        const int i  = (b >> 1) & 31;
        const int ch = (b & 1) << 5;
        {
            int c = t >> 3, j4 = (t & 7) << 2;
            float4 v = *(const float4*)&x[((n * 64 + ch + c) * 32 + i) * 32 + j4];
            s[c][j4] = v.x; s[c][j4 + 1] = v.y; s[c][j4 + 2] = v.z; s[c][j4 + 3] = v.w;
        }
        __syncthreads();
        #pragma unroll
        for (int k = 0; k < 4; k++) {
            int idx = t + k * 256;
            int j = idx >> 5, c = idx & 31;
            g_xt[((n * 32 + i) * 32 + j) * 64 + ch + c] = s[c][j];
        }
    } else {
        // pack weights: wpk[base + ((l*8+g)*ntap + tp)*8 + m]
        for (int w = t; w < 4608; w += 256) {
            int cls, rem, ntap;
            if (w < 512)       { cls = 0; rem = w;        ntap = 1; }
            else if (w < 1536) { cls = 1; rem = w - 512;  ntap = 2; }
            else if (w < 2560) { cls = 2; rem = w - 1536; ntap = 2; }
            else               { cls = 3; rem = w - 2560; ntap = 4; }
            int m  = rem & 7;
            int e  = rem >> 3;          // (l*8+g)*ntap + tp
            int tp = e % ntap;
            int lg = e / ntap;          // l*8 + g
            int kh, kw;
            if (cls == 0)      { kh = 1;              kw = 1; }
            else if (cls == 1) { kh = 1;              kw = tp << 1; }
            else if (cls == 2) { kh = tp << 1;        kw = 1; }
            else               { kh = (tp >> 1) << 1; kw = (tp & 1) << 1; }
            int woff = (2 - kh) * 3 + (2 - kw);       // flipped kernel tap
            g_wpk[w] = wt[(lg * 8 + m) * 9 + woff];
        }
    }
}

// packed reduce-scatter over width 8: v[4] f32x2 regs -> fully-summed
// component r on lane r. 7 shuffle wavefronts (2x shfl64, 1x shfl64, 1x shfl32).
__device__ __forceinline__ float rs8p(const ull v[4], int r)
{
    const unsigned FULL = 0xffffffffu;
    const bool b4 = (r & 4) != 0, b2 = (r & 2) != 0, b1 = (r & 1) != 0;
    ull s0 = b4 ? v[0] : v[2];
    ull s1 = b4 ? v[1] : v[3];
    ull k0 = b4 ? v[2] : v[0];
    ull k1 = b4 ? v[3] : v[1];
    ull w0 = add2(k0, __shfl_xor_sync(FULL, s0, 4, 8));
    ull w1 = add2(k1, __shfl_xor_sync(FULL, s1, 4, 8));
    ull su = b2 ? w0 : w1;
    ull ku = b2 ? w1 : w0;
    ull u  = add2(ku, __shfl_xor_sync(FULL, su, 2, 8));
    float ua, ub; unpack2(u, ua, ub);
    float sf = b1 ? ua : ub;
    float kf = b1 ? ub : ua;
    return kf + __shfl_xor_sync(FULL, sf, 1, 8);
}

// all-gather over width 8: scalar s (component r on lane r) -> o2[4] packed.
// 7 shuffle wavefronts.
__device__ __forceinline__ void ag8p(float s, int r, ull o2[4])
{
    const unsigned FULL = 0xffffffffu;
    const bool b4 = (r & 4) != 0, b2 = (r & 2) != 0, b1 = (r & 1) != 0;
    float t = __shfl_xor_sync(FULL, s, 1, 8);
    float lo = b1 ? t : s;
    float hi = b1 ? s : t;
    ull u  = pack2(lo, hi);
    ull t2 = __shfl_xor_sync(FULL, u, 2, 8);
    ull w0 = b2 ? t2 : u;
    ull w1 = b2 ? u : t2;
    ull t0 = __shfl_xor_sync(FULL, w0, 4, 8);
    ull t1 = __shfl_xor_sync(FULL, w1, 4, 8);
    o2[0] = b4 ? t0 : w0;
    o2[1] = b4 ? t1 : w1;
    o2[2] = b4 ? w0 : t0;
    o2[3] = b4 ? w1 : t1;
}

// routing + squash + store; priors packed: pri2[k][j] = (m=2j, m=2j+1)
template<int CNT>
__device__ __forceinline__ void route_and_store(
    ull pri2[CNT][4], int n, int p, int q,
    const float* __restrict__ bs, float* __restrict__ y)
{
    constexpr float NZEROS = (float)(72 - 8 * CNT);
    const unsigned FULL = 0xffffffffu;
    const int tid = threadIdx.x;
    const int r = tid & 7;

    // init: out0 = mean of 72 priors; only its DIRECTION is used, so skip /72
    ull o2[4];
    #pragma unroll
    for (int j = 0; j < 4; j++) o2[j] = pri2[0][j];
    #pragma unroll
    for (int k = 1; k < CNT; k++)
        #pragma unroll
        for (int j = 0; j < 4; j++) o2[j] = add2(o2[j], pri2[k][j]);
    {
        float s0 = rs8p(o2, r);
        ag8p(s0, r, o2);
    }

    // iterations 0,1: Z cancels (next iter only uses acc/||acc||), so o2
    // carries the UNNORMALIZED weighted sum; inv absorbs the scale.
    #pragma unroll
    for (int it = 0; it < 2; it++) {
        ull t = mul2(o2[0], o2[0]);
        t = fma2(o2[1], o2[1], t);
        t = fma2(o2[2], o2[2], t);
        t = fma2(o2[3], o2[3], t);
        float ta, tb; unpack2(t, ta, tb);
        float inv = rsqrtf(fmaxf(ta + tb, 1e-24f));

        float e[CNT];
        #pragma unroll
        for (int k = 0; k < CNT; k++) {
            ull s = mul2(pri2[k][0], o2[0]);
            s = fma2(pri2[k][1], o2[1], s);
            s = fma2(pri2[k][2], o2[2], s);
            s = fma2(pri2[k][3], o2[3], s);
            float sa, sb; unpack2(s, sa, sb);
            e[k] = __expf((sa + sb) * inv);
        }

        ull acc2[4];
        {
            ull e2 = pack2(e[0], e[0]);
            #pragma unroll
            for (int j = 0; j < 4; j++) acc2[j] = mul2(e2, pri2[0][j]);
        }
        #pragma unroll
        for (int k = 1; k < CNT; k++) {
            ull e2 = pack2(e[k], e[k]);
            #pragma unroll
            for (int j = 0; j < 4; j++) acc2[j] = fma2(e2, pri2[k][j], acc2[j]);
        }

        float s = rs8p(acc2, r);
        ag8p(s, r, o2);
    }

    // final iteration: true magnitude needed -> compute Z (zero priors: +NZEROS)
    {
        ull t = mul2(o2[0], o2[0]);
        t = fma2(o2[1], o2[1], t);
        t = fma2(o2[2], o2[2], t);
        t = fma2(o2[3], o2[3], t);
        float ta, tb; unpack2(t, ta, tb);
        float inv = rsqrtf(fmaxf(ta + tb, 1e-24f));

        float e[CNT];
        float z = 0.f;
        #pragma unroll
        for (int k = 0; k < CNT; k++) {
            ull s = mul2(pri2[k][0], o2[0]);
            s = fma2(pri2[k][1], o2[1], s);
            s = fma2(pri2[k][2], o2[2], s);
            s = fma2(pri2[k][3], o2[3], s);
            float sa, sb; unpack2(s, sa, sb);
            e[k] = __expf((sa + sb) * inv);
            z += e[k];
        }
        z += __shfl_xor_sync(FULL, z, 1, 8);
        z += __shfl_xor_sync(FULL, z, 2, 8);
        z += __shfl_xor_sync(FULL, z, 4, 8);
        z += NZEROS;

        ull acc2[4];
        {
            ull e2 = pack2(e[0], e[0]);
            #pragma unroll
            for (int j = 0; j < 4; j++) acc2[j] = mul2(e2, pri2[0][j]);
        }
        #pragma unroll
        for (int k = 1; k < CNT; k++) {
            ull e2 = pack2(e[k], e[k]);
            #pragma unroll
            for (int j = 0; j < 4; j++) acc2[j] = fma2(e2, pri2[k][j], acc2[j]);
        }

        float s   = rs8p(acc2, r);               // component r, fully summed
        float orr = s * __fdividef(1.0f, z);

        float sq = orr * orr;                     // ||out||^2 via 3 shuffles
        sq += __shfl_xor_sync(FULL, sq, 1, 8);
        sq += __shfl_xor_sync(FULL, sq, 2, 8);
        sq += __shfl_xor_sync(FULL, sq, 4, 8);

        float scale = sq / ((1.0f + sq) * sqrtf(sq + 1e-12f));
        y[((n * 64 + tid) * 64 + p) * 64 + q] = orr * scale + bs[tid];
    }
}

__device__ __forceinline__ void load8(float dst[8], const float* src, bool valid)
{
    if (valid) {
        float4 u0 = *(const float4*)(src);
        float4 u1 = *(const float4*)(src + 4);
        dst[0] = u0.x; dst[1] = u0.y; dst[2] = u0.z; dst[3] = u0.w;
        dst[4] = u1.x; dst[5] = u1.y; dst[6] = u1.z; dst[7] = u1.w;
    } else {
        #pragma unroll
        for (int i = 0; i < 8; i++) dst[i] = 0.f;
    }
}

// NTAP<=2 classes: x direct from g_xt (registers), packed-FMA priors.
template<int NTAP, int BASE>
__device__ __forceinline__ void caps_direct(
    int n, int p, int q, int i0, int j0, bool ivar,   // ivar: tap varies i (OE)
    const float* __restrict__ bs, float* __restrict__ y)
{
    const int tid = threadIdx.x;
    const int g = tid >> 3;
    const int r = tid & 7;
    const int tp = r & (NTAP - 1);
    const int f0 = r / NTAP;

    float xr[NTAP][8];   // [k][l], fields f0 + k*(8/NTAP)
    if (NTAP == 1) {
        const float* xb = g_xt + ((n * 32 + i0) * 32 + j0) * 64 + f0 * 8;
        load8(xr[0], xb, true);
    } else {
        int i = ivar ? (i0 + tp) : i0;
        int j = ivar ? j0 : (j0 + tp);
        bool valid = (i < 32) && (j < 32);     // tap 2 at p/q == 63
        const float* xb = g_xt + ((n * 32 + i) * 32 + j) * 64;
        load8(xr[0], xb + f0 * 8, valid);
        load8(xr[1], xb + (f0 + 4) * 8, valid);
    }

    const float* wrow = g_wpk + BASE + (g * NTAP + tp) * 8;

    ull pri2[NTAP][4];
    #pragma unroll
    for (int k = 0; k < NTAP; k++)
        #pragma unroll
        for (int j = 0; j < 4; j++) pri2[k][j] = 0ull;

    #pragma unroll
    for (int l = 0; l < 8; l++) {
        const ulonglong2* wp = (const ulonglong2*)(wrow + l * (64 * NTAP));
        ulonglong2 wa = wp[0];            // (m0,m1),(m2,m3)
        ulonglong2 wb = wp[1];            // (m4,m5),(m6,m7)
        #pragma unroll
        for (int k = 0; k < NTAP; k++) {
            ull xx = pack2(xr[k][l], xr[k][l]);
            pri2[k][0] = fma2(xx, wa.x, pri2[k][0]);
            pri2[k][1] = fma2(xx, wa.y, pri2[k][1]);
            pri2[k][2] = fma2(xx, wb.x, pri2[k][2]);
            pri2[k][3] = fma2(xx, wb.y, pri2[k][3]);
        }
    }

    route_and_store<NTAP>(pri2, n, p, q, bs, y);
}

// OO class: x staged in smem, layout s_x[f*34 + pos*8 + l] -> LDS.64 reads,
// conflict-free (banks 2f + 8tp + l distinct per instruction), 8B-aligned.
__device__ __forceinline__ void caps_oo(
    int n, int p, int q, float* __restrict__ s_x,
    const float* __restrict__ bs, float* __restrict__ y)
{
    const int tid = threadIdx.x;
    const int g = tid >> 3;
    const int r = tid & 7;

    const int i0 = p >> 1, j0 = q >> 1;   // p,q odd: (p-1)/2
    const int fw = tid >> 3, lw = tid & 7;
    #pragma unroll
    for (int pos = 0; pos < 4; pos++) {
        int i = i0 + (pos >> 1);
        int j = j0 + (pos & 1);
        bool valid = (i < 32) && (j < 32);
        float v = valid ? g_xt[((n * 32 + i) * 32 + j) * 64 + tid] : 0.f;
        s_x[fw * 34 + pos * 8 + lw] = v;
    }
    __syncthreads();

    const int tp = r & 3;
    const int f0 = r >> 2;
    const float* wrow = g_wpk + 2560 + (g * 4 + tp) * 8;
    const float* xrow = s_x + f0 * 34 + tp * 8;   // field f0+2k -> + k*68

    ull pri2[4][4];
    #pragma unroll
    for (int k = 0; k < 4; k++)
        #pragma unroll
        for (int j = 0; j < 4; j++) pri2[k][j] = 0ull;

    #pragma unroll
    for (int l2 = 0; l2 < 4; l2++) {
        const int l = l2 * 2;
        const ulonglong2* wpA = (const ulonglong2*)(wrow + l * 256);
        const ulonglong2* wpB = (const ulonglong2*)(wrow + (l + 1) * 256);
        ulonglong2 wa = wpA[0], wb = wpA[1];
        ulonglong2 wc = wpB[0], wd = wpB[1];
        #pragma unroll
        for (int k = 0; k < 4; k++) {
            float2 xv = *(const float2*)(xrow + k * 68 + l);   // LDS.64
            ull x0 = pack2(xv.x, xv.x);
            ull x1 = pack2(xv.y, xv.y);
            pri2[k][0] = fma2(x0, wa.x, pri2[k][0]);
            pri2[k][1] = fma2(x0, wa.y, pri2[k][1]);
            pri2[k][2] = fma2(x0, wb.x, pri2[k][2]);
            pri2[k][3] = fma2(x0, wb.y, pri2[k][3]);
            pri2[k][0] = fma2(x1, wc.x, pri2[k][0]);
            pri2[k][1] = fma2(x1, wc.y, pri2[k][1]);
            pri2[k][2] = fma2(x1, wd.x, pri2[k][2]);
            pri2[k][3] = fma2(x1, wd.y, pri2[k][3]);
        }
    }

    route_and_store<4>(pri2, n, p, q, bs, y);
}

__global__ __launch_bounds__(64, 16)
void caps_kernel(const float* __restrict__ bs, float* __restrict__ y)
{
    __shared__ float s_x[8 * 34];

    const int pix = blockIdx.x;
    const int q = pix & 63;
    const int p = (pix >> 6) & 63;
    const int n = pix >> 12;

    const bool po = (p & 1) != 0;
    const bool qo = (q & 1) != 0;

    if (!po && !qo)
        caps_direct<1, 0>(n, p, q, p >> 1, q >> 1, false, bs, y);
    else if (!po)
        caps_direct<2, 512>(n, p, q, p >> 1, q >> 1, false, bs, y);   // j = j0+tp
    else if (!qo)
        caps_direct<2, 1536>(n, p, q, p >> 1, q >> 1, true, bs, y);   // i = i0+tp
    else
        caps_oo(n, p, q, s_x, bs, y);
}

extern "C" void kernel_launch(void* const* d_in, const int* in_sizes, int n_in,
                              void* d_out, int out_size) {
    const float* x  = (const float*)d_in[0];
    const float* wt = (const float*)d_in[1];
    const float* bs = (const float*)d_in[2];
    float* y = (float*)d_out;
    prep_kernel<<<129, 256>>>(x, wt);
    caps_kernel<<<2 * 64 * 64, 64>>>(bs, y);
}